// round 13
// baseline (speedup 1.0000x reference)
#include <cuda_runtime.h>

// Problem constants
#define BB   512
#define TT   65536
#define CL   128                  // chunk length (samples per thread)
#define NC   (TT / CL)            // 512 chunks per row
#define WUS  4                    // warm-up stages of 32 (128 samples = 1 chunk)
#define NTH  128                  // 4 warps; each warp owns 32 chunks
#define NRP  (BB / 2)             // 256 row pairs
#define GRID (NRP * 4)            // 1024 blocks

#define BUF_F4   (NTH * 9)
#define SMEM_STG (2 * BUF_F4 * 16)    // 36864 bytes

typedef unsigned long long u64f;

// Intermediate: y1 transposed-packed: yt[iw * NC + c], iw = within-chunk index
// (0..127), c = chunk (0..511); packs the two rows of the pair (lo=r0, hi=r1).
__device__ __align__(16) u64f g_y1t[(size_t)NRP * TT];   // 128 MB

// ---------------------------------------------------------------------------
#define FFMA2(d, a, b, c) asm("fma.rn.f32x2 %0, %1, %2, %3;" : "=l"(d) : "l"(a), "l"(b), "l"(c))

__device__ __forceinline__ u64f pk2(float lo, float hi) {
    u64f r; asm("mov.b64 %0, {%1, %2};" : "=l"(r) : "f"(lo), "f"(hi)); return r;
}
__device__ __forceinline__ float2 upk(u64f v) {
    float2 r; asm("mov.b64 {%0, %1}, %2;" : "=f"(r.x), "=f"(r.y) : "l"(v)); return r;
}

__device__ __forceinline__ u64f pstep(u64f x, u64f* z, const u64f* cb, const u64f* cna) {
    u64f y, t;
    FFMA2(y, cb[0], x, z[0]);
    #pragma unroll
    for (int i = 0; i < 7; i++) {
        FFMA2(t, cb[i + 1], x, z[i + 1]);
        FFMA2(z[i], cna[i], y, t);
    }
    u64f zz = 0ULL;
    FFMA2(t, cb[8], x, zz);
    FFMA2(z[7], cna[7], y, t);
    return y;
}

__device__ __forceinline__ void load_coef_inline(const float* __restrict__ bp,
                                                 const float* __restrict__ ap,
                                                 u64f* cb, u64f* cna) {
    float inv = 1.0f / __ldg(&ap[0]);
    #pragma unroll
    for (int i = 0; i < 9; i++) {
        float bn = __ldg(&bp[i]) * inv;
        cb[i] = pk2(bn, bn);
    }
    #pragma unroll
    for (int i = 1; i < 9; i++) {
        float an = -(__ldg(&ap[i]) * inv);
        cna[i - 1] = pk2(an, an);
    }
}

// ---------------------------------------------------------------------------
// fwd: warp-autonomous. Each warp owns 32 consecutive chunks (one per lane);
// per 32-sample stage it cooperatively loads its own smem region (coalesced),
// __syncwarp, consumes, __syncwarp. Warm-up = previous chunk (128 samples),
// then own 128 samples, y written to y1T inline (coalesced STG.64).
// ---------------------------------------------------------------------------
__global__ void __launch_bounds__(NTH) fwd_k(const float* __restrict__ x,
                                             const float* __restrict__ bp,
                                             const float* __restrict__ ap) {
    extern __shared__ char smc[];
    float4* b0 = (float4*)smc;
    float4* b1 = b0 + BUF_F4;

    int rp = blockIdx.x >> 2, h = blockIdx.x & 3, t = threadIdx.x;
    int w = t >> 5, ln = t & 31;
    int wcb = (h * 4 + w) * 32;          // warp's first chunk (0..480)
    int c = wcb + ln;                    // this lane's chunk
    const float* p0 = x + (size_t)(rp * 2) * TT;
    const float* p1 = p0 + TT;
    u64f* yt = g_y1t + (size_t)rp * TT;

    float4* w0 = b0 + w * (32 * 9);      // warp-private staging, row0
    float4* w1 = b1 + w * (32 * 9);      // row1

    u64f cb[9], cna[8];
    load_coef_inline(bp, ap, cb, cna);

    u64f z[8];
    #pragma unroll
    for (int i2 = 0; i2 < 8; i2++) z[i2] = 0ULL;

    #pragma unroll 1
    for (int k = 0; k < 4 + WUS; k++) {
        // cooperative warp load: local slot tt gets stage (wcb+tt)*4 + k - WUS
        #pragma unroll
        for (int l = 0; l < 8; l++) {
            int q = l * 32 + ln;
            int tt = q >> 3, j = q & 7;
            int sg = (wcb + tt) * 4 + (k - WUS);
            float4 va = make_float4(0.f, 0.f, 0.f, 0.f);
            float4 vb = va;
            if (sg >= 0) {
                int base = sg * 32 + 4 * j;
                va = *reinterpret_cast<const float4*>(p0 + base);
                vb = *reinterpret_cast<const float4*>(p1 + base);
            }
            w0[tt * 9 + j] = va;
            w1[tt * 9 + j] = vb;
        }
        __syncwarp();
        if (k < WUS) {
            #pragma unroll
            for (int j2 = 0; j2 < 8; j2++) {
                float4 a4 = w0[ln * 9 + j2];
                float4 c4 = w1[ln * 9 + j2];
                pstep(pk2(a4.x, c4.x), z, cb, cna);
                pstep(pk2(a4.y, c4.y), z, cb, cna);
                pstep(pk2(a4.z, c4.z), z, cb, cna);
                pstep(pk2(a4.w, c4.w), z, cb, cna);
            }
        } else {
            #pragma unroll
            for (int j2 = 0; j2 < 8; j2++) {
                float4 a4 = w0[ln * 9 + j2];
                float4 c4 = w1[ln * 9 + j2];
                u64f yp0 = pstep(pk2(a4.x, c4.x), z, cb, cna);
                u64f yp1 = pstep(pk2(a4.y, c4.y), z, cb, cna);
                u64f yp2 = pstep(pk2(a4.z, c4.z), z, cb, cna);
                u64f yp3 = pstep(pk2(a4.w, c4.w), z, cb, cna);
                int iw = (k - WUS) * 32 + 4 * j2;    // within-chunk index 0..127
                yt[(size_t)(iw + 0) * NC + c] = yp0;
                yt[(size_t)(iw + 1) * NC + c] = yp1;
                yt[(size_t)(iw + 2) * NC + c] = yp2;
                yt[(size_t)(iw + 3) * NC + c] = yp3;
            }
        }
        __syncwarp();
    }
}

// ---------------------------------------------------------------------------
// bwd: warp-autonomous time-reversed filter over y1T. Direct coalesced LDG.64
// with depth-2 rolling register prefetch. Warm-up = chunk c+1 (128 samples,
// L1/L2-local duplicates of neighbor threads' reads). Output staged to
// physical layout via warp-private smem (+__syncwarp only).
// ---------------------------------------------------------------------------
__global__ void __launch_bounds__(NTH) bwd_k(float* __restrict__ out,
                                             const float* __restrict__ bp,
                                             const float* __restrict__ ap) {
    extern __shared__ char smc[];
    float4* b0 = (float4*)smc;
    float4* b1 = b0 + BUF_F4;

    int rp = blockIdx.x >> 2, h = blockIdx.x & 3, t = threadIdx.x;
    int w = t >> 5, ln = t & 31;
    int wcb = (h * 4 + w) * 32;
    int c = wcb + ln;                    // this lane's chunk (0..511)
    const u64f* yt = g_y1t + (size_t)rp * TT;
    float* o0 = out + (size_t)(rp * 2) * TT;
    float* o1 = o0 + TT;

    float4* w0 = b0 + w * (32 * 9);
    float4* w1 = b1 + w * (32 * 9);

    u64f cb[9], cna[8];
    load_coef_inline(bp, ap, cb, cna);

    u64f z[8];
    #pragma unroll
    for (int i2 = 0; i2 < 8; i2++) z[i2] = 0ULL;

    // ---- warm-up: chunk c+1, iw = 127 down to 0, depth-2 prefetch ----
    {
        bool valid = (c + 1 < NC);
        const u64f* base = yt + (valid ? (c + 1) : c);
        u64f A0, A1, A2, A3, B0, B1, B2, B3;
        A3 = valid ? base[(size_t)127 * NC] : 0ULL;
        A2 = valid ? base[(size_t)126 * NC] : 0ULL;
        A1 = valid ? base[(size_t)125 * NC] : 0ULL;
        A0 = valid ? base[(size_t)124 * NC] : 0ULL;
        B3 = valid ? base[(size_t)123 * NC] : 0ULL;
        B2 = valid ? base[(size_t)122 * NC] : 0ULL;
        B1 = valid ? base[(size_t)121 * NC] : 0ULL;
        B0 = valid ? base[(size_t)120 * NC] : 0ULL;
        #pragma unroll 2
        for (int p = 0; p < WUS * 8; p++) {
            u64f x3 = A3, x2 = A2, x1 = A1, x0 = A0;
            A3 = B3; A2 = B2; A1 = B1; A0 = B0;
            int nt = 127 - 4 * (p + 2);
            if (p + 2 < WUS * 8) {
                B3 = valid ? base[(size_t)(nt - 0) * NC] : 0ULL;
                B2 = valid ? base[(size_t)(nt - 1) * NC] : 0ULL;
                B1 = valid ? base[(size_t)(nt - 2) * NC] : 0ULL;
                B0 = valid ? base[(size_t)(nt - 3) * NC] : 0ULL;
            }
            pstep(x3, z, cb, cna);
            pstep(x2, z, cb, cna);
            pstep(x1, z, cb, cna);
            pstep(x0, z, cb, cna);
        }
    }

    // ---- own chunk: iw = 127 down to 0, depth-2 prefetch, staged output ----
    {
        const u64f* base = yt + c;
        u64f A0, A1, A2, A3, B0, B1, B2, B3;
        A3 = base[(size_t)127 * NC];
        A2 = base[(size_t)126 * NC];
        A1 = base[(size_t)125 * NC];
        A0 = base[(size_t)124 * NC];
        B3 = base[(size_t)123 * NC];
        B2 = base[(size_t)122 * NC];
        B1 = base[(size_t)121 * NC];
        B0 = base[(size_t)120 * NC];
        #pragma unroll 1
        for (int g = 0; g < 4; g++) {
            int iwb = 96 - 32 * g;           // base of this 32-sample group
            #pragma unroll
            for (int g4 = 0; g4 < 8; g4++) {
                int p = g * 8 + g4;
                u64f x3 = A3, x2 = A2, x1 = A1, x0 = A0;
                A3 = B3; A2 = B2; A1 = B1; A0 = B0;
                int nt = 127 - 4 * (p + 2);
                if (p + 2 < 32) {
                    B3 = base[(size_t)(nt - 0) * NC];
                    B2 = base[(size_t)(nt - 1) * NC];
                    B1 = base[(size_t)(nt - 2) * NC];
                    B0 = base[(size_t)(nt - 3) * NC];
                }
                float2 y3 = upk(pstep(x3, z, cb, cna));   // iw3
                float2 y2 = upk(pstep(x2, z, cb, cna));   // iw3-1
                float2 y1v = upk(pstep(x1, z, cb, cna));  // iw3-2
                float2 y0 = upk(pstep(x0, z, cb, cna));   // iw3-3
                int jl = 7 - g4;
                w0[ln * 9 + jl] = make_float4(y0.x, y1v.x, y2.x, y3.x);
                w1[ln * 9 + jl] = make_float4(y0.y, y1v.y, y2.y, y3.y);
            }
            __syncwarp();
            #pragma unroll
            for (int l = 0; l < 8; l++) {
                int q = l * 32 + ln;
                int tt = q >> 3, j = q & 7;
                int cc = wcb + tt;
                int base2 = cc * CL + iwb + 4 * j;
                *reinterpret_cast<float4*>(o0 + base2) = w0[tt * 9 + j];
                *reinterpret_cast<float4*>(o1 + base2) = w1[tt * 9 + j];
            }
            __syncwarp();
        }
    }
}

extern "C" void kernel_launch(void* const* d_in, const int* in_sizes, int n_in,
                              void* d_out, int out_size) {
    const float* x = (const float*)d_in[0];
    const float* b = (const float*)d_in[1];
    const float* a = (const float*)d_in[2];
    float* out = (float*)d_out;

    static bool attr_done = false;
    if (!attr_done) {
        cudaFuncSetAttribute(fwd_k, cudaFuncAttributeMaxDynamicSharedMemorySize, SMEM_STG);
        cudaFuncSetAttribute(bwd_k, cudaFuncAttributeMaxDynamicSharedMemorySize, SMEM_STG);
        attr_done = true;
    }

    fwd_k<<<GRID, NTH, SMEM_STG>>>(x, b, a);
    bwd_k<<<GRID, NTH, SMEM_STG>>>(out, b, a);
}

// round 14
// speedup vs baseline: 1.1680x; 1.1680x over previous
#include <cuda_runtime.h>
#include <cuda_fp16.h>

// Problem constants
#define BB   512
#define TT   65536
#define CL   256                  // chunk length (samples per thread)
#define NC   (TT / CL)            // 256 chunks per row
#define WUS  5                    // warm-up stages (160 samples, decay ~2.6e-6)
#define NTH  128                  // 4 warps; each warp owns 32 chunks
#define NRP  (BB / 2)             // 256 row pairs
#define GRID (NRP * 2)            // 512 blocks

#define BUF_F4   (NTH * 9)
#define SMEM_STG (2 * BUF_F4 * 16)    // 36864 bytes

typedef unsigned long long u64f;
typedef unsigned int u32h;

// Intermediate: y1 transposed-packed in HALF precision: yt[iw * NC + c] is a
// half2 packing the two rows of the pair (lo=row0, hi=row1). 64 MB total.
__device__ __align__(16) u32h g_y1t[(size_t)NRP * TT];

// ---------------------------------------------------------------------------
#define FFMA2(d, a, b, c) asm("fma.rn.f32x2 %0, %1, %2, %3;" : "=l"(d) : "l"(a), "l"(b), "l"(c))

__device__ __forceinline__ u64f pk2(float lo, float hi) {
    u64f r; asm("mov.b64 %0, {%1, %2};" : "=l"(r) : "f"(lo), "f"(hi)); return r;
}
__device__ __forceinline__ float2 upk(u64f v) {
    float2 r; asm("mov.b64 {%0, %1}, %2;" : "=f"(r.x), "=f"(r.y) : "l"(v)); return r;
}

// packed f32x2 -> half2 (lo stays low)
__device__ __forceinline__ u32h f2_to_h2(u64f v) {
    float2 f = upk(v);
    u32h r;
    asm("cvt.rn.f16x2.f32 %0, %1, %2;" : "=r"(r) : "f"(f.y), "f"(f.x));
    return r;
}
// half2 -> packed f32x2
__device__ __forceinline__ u64f h2_to_f2(u32h v) {
    float lo, hi;
    asm("{\n\t.reg .f16 l, h;\n\tmov.b32 {l, h}, %2;\n\t"
        "cvt.f32.f16 %0, l;\n\tcvt.f32.f16 %1, h;\n\t}"
        : "=f"(lo), "=f"(hi) : "r"(v));
    return pk2(lo, hi);
}

__device__ __forceinline__ u64f pstep(u64f x, u64f* z, const u64f* cb, const u64f* cna) {
    u64f y, t;
    FFMA2(y, cb[0], x, z[0]);
    #pragma unroll
    for (int i = 0; i < 7; i++) {
        FFMA2(t, cb[i + 1], x, z[i + 1]);
        FFMA2(z[i], cna[i], y, t);
    }
    u64f zz = 0ULL;
    FFMA2(t, cb[8], x, zz);
    FFMA2(z[7], cna[7], y, t);
    return y;
}

__device__ __forceinline__ void load_coef_inline(const float* __restrict__ bp,
                                                 const float* __restrict__ ap,
                                                 u64f* cb, u64f* cna) {
    float inv = 1.0f / __ldg(&ap[0]);
    #pragma unroll
    for (int i = 0; i < 9; i++) {
        float bn = __ldg(&bp[i]) * inv;
        cb[i] = pk2(bn, bn);
    }
    #pragma unroll
    for (int i = 1; i < 9; i++) {
        float an = -(__ldg(&ap[i]) * inv);
        cna[i - 1] = pk2(an, an);
    }
}

// ---------------------------------------------------------------------------
// fwd: warp-autonomous (identical structure to the 171us kernel). Warm-up =
// 160 samples preceding the chunk, then 256 own samples; y written to y1T in
// HALF2 (coalesced STG.32 across lanes, 128B/warp).
// ---------------------------------------------------------------------------
__global__ void __launch_bounds__(NTH) fwd_k(const float* __restrict__ x,
                                             const float* __restrict__ bp,
                                             const float* __restrict__ ap) {
    extern __shared__ char smc[];
    float4* b0 = (float4*)smc;
    float4* b1 = b0 + BUF_F4;

    int rp = blockIdx.x >> 1, h = blockIdx.x & 1, t = threadIdx.x;
    int w = t >> 5, ln = t & 31;
    int wcb = (h * 4 + w) * 32;          // warp's first chunk
    int c = wcb + ln;                    // this lane's chunk
    const float* p0 = x + (size_t)(rp * 2) * TT;
    const float* p1 = p0 + TT;
    u32h* yt = g_y1t + (size_t)rp * TT;

    float4* w0 = b0 + w * (32 * 9);      // warp-private staging, row0
    float4* w1 = b1 + w * (32 * 9);      // row1

    u64f cb[9], cna[8];
    load_coef_inline(bp, ap, cb, cna);

    u64f z[8];
    #pragma unroll
    for (int i2 = 0; i2 < 8; i2++) z[i2] = 0ULL;

    #pragma unroll 1
    for (int k = 0; k < 8 + WUS; k++) {
        // cooperative warp load: local slot tt gets stage (wcb+tt)*8 + k - WUS
        #pragma unroll
        for (int l = 0; l < 8; l++) {
            int q = l * 32 + ln;
            int tt = q >> 3, j = q & 7;
            int sg = (wcb + tt) * 8 + (k - WUS);
            float4 va = make_float4(0.f, 0.f, 0.f, 0.f);
            float4 vb = va;
            if (sg >= 0) {
                int base = sg * 32 + 4 * j;
                va = *reinterpret_cast<const float4*>(p0 + base);
                vb = *reinterpret_cast<const float4*>(p1 + base);
            }
            w0[tt * 9 + j] = va;
            w1[tt * 9 + j] = vb;
        }
        __syncwarp();
        if (k < WUS) {
            #pragma unroll
            for (int j2 = 0; j2 < 8; j2++) {
                float4 a4 = w0[ln * 9 + j2];
                float4 c4 = w1[ln * 9 + j2];
                pstep(pk2(a4.x, c4.x), z, cb, cna);
                pstep(pk2(a4.y, c4.y), z, cb, cna);
                pstep(pk2(a4.z, c4.z), z, cb, cna);
                pstep(pk2(a4.w, c4.w), z, cb, cna);
            }
        } else {
            #pragma unroll
            for (int j2 = 0; j2 < 8; j2++) {
                float4 a4 = w0[ln * 9 + j2];
                float4 c4 = w1[ln * 9 + j2];
                u64f yp0 = pstep(pk2(a4.x, c4.x), z, cb, cna);
                u64f yp1 = pstep(pk2(a4.y, c4.y), z, cb, cna);
                u64f yp2 = pstep(pk2(a4.z, c4.z), z, cb, cna);
                u64f yp3 = pstep(pk2(a4.w, c4.w), z, cb, cna);
                int iw = (k - WUS) * 32 + 4 * j2;    // within-chunk index 0..255
                yt[(size_t)(iw + 0) * NC + c] = f2_to_h2(yp0);
                yt[(size_t)(iw + 1) * NC + c] = f2_to_h2(yp1);
                yt[(size_t)(iw + 2) * NC + c] = f2_to_h2(yp2);
                yt[(size_t)(iw + 3) * NC + c] = f2_to_h2(yp3);
            }
        }
        __syncwarp();
    }
}

// ---------------------------------------------------------------------------
// bwd: warp-autonomous time-reversed filter over half2 y1T. Direct coalesced
// LDG.32 with rolling register prefetch; fp32 math after unpack. Output staged
// to physical layout via warp-private smem (+__syncwarp only).
// ---------------------------------------------------------------------------
__global__ void __launch_bounds__(NTH) bwd_k(float* __restrict__ out,
                                             const float* __restrict__ bp,
                                             const float* __restrict__ ap) {
    extern __shared__ char smc[];
    float4* b0 = (float4*)smc;
    float4* b1 = b0 + BUF_F4;

    int rp = blockIdx.x >> 1, h = blockIdx.x & 1, t = threadIdx.x;
    int w = t >> 5, ln = t & 31;
    int wcb = (h * 4 + w) * 32;
    int c = wcb + ln;                    // this lane's chunk
    const u32h* yt = g_y1t + (size_t)rp * TT;
    float* o0 = out + (size_t)(rp * 2) * TT;
    float* o1 = o0 + TT;

    float4* w0 = b0 + w * (32 * 9);
    float4* w1 = b1 + w * (32 * 9);

    u64f cb[9], cna[8];
    load_coef_inline(bp, ap, cb, cna);

    u64f z[8];
    #pragma unroll
    for (int i2 = 0; i2 < 8; i2++) z[i2] = 0ULL;

    // ---- warm-up: chunk c+1, iw = 159 down to 0, rolling prefetch ----
    {
        bool valid = (c + 1 < NC);
        const u32h* base = yt + (valid ? (c + 1) : c);
        u32h nx0, nx1, nx2, nx3;
        nx3 = valid ? base[(size_t)159 * NC] : 0u;
        nx2 = valid ? base[(size_t)158 * NC] : 0u;
        nx1 = valid ? base[(size_t)157 * NC] : 0u;
        nx0 = valid ? base[(size_t)156 * NC] : 0u;
        #pragma unroll 1
        for (int p = 0; p < WUS * 8; p++) {
            u32h x3 = nx3, x2 = nx2, x1 = nx1, x0 = nx0;
            int niw3 = 159 - 4 * (p + 1);
            if (p + 1 < WUS * 8) {
                nx3 = valid ? base[(size_t)(niw3 - 0) * NC] : 0u;
                nx2 = valid ? base[(size_t)(niw3 - 1) * NC] : 0u;
                nx1 = valid ? base[(size_t)(niw3 - 2) * NC] : 0u;
                nx0 = valid ? base[(size_t)(niw3 - 3) * NC] : 0u;
            }
            pstep(h2_to_f2(x3), z, cb, cna);
            pstep(h2_to_f2(x2), z, cb, cna);
            pstep(h2_to_f2(x1), z, cb, cna);
            pstep(h2_to_f2(x0), z, cb, cna);
        }
    }

    // ---- own chunk: iw = 255 down to 0, prefetch; warp-staged output ----
    {
        const u32h* base = yt + c;
        u32h nx0, nx1, nx2, nx3;
        nx3 = base[(size_t)255 * NC];
        nx2 = base[(size_t)254 * NC];
        nx1 = base[(size_t)253 * NC];
        nx0 = base[(size_t)252 * NC];
        #pragma unroll 1
        for (int g = 0; g < 8; g++) {
            int iwb = 224 - 32 * g;          // base of this 32-sample group
            #pragma unroll
            for (int g4 = 0; g4 < 8; g4++) {
                u32h x3 = nx3, x2 = nx2, x1 = nx1, x0 = nx0;
                int iw3 = iwb + 31 - 4 * g4;
                int niw3 = iw3 - 4;
                if (niw3 >= 3) {
                    nx3 = base[(size_t)(niw3 - 0) * NC];
                    nx2 = base[(size_t)(niw3 - 1) * NC];
                    nx1 = base[(size_t)(niw3 - 2) * NC];
                    nx0 = base[(size_t)(niw3 - 3) * NC];
                }
                float2 y3 = upk(pstep(h2_to_f2(x3), z, cb, cna));   // iw3
                float2 y2 = upk(pstep(h2_to_f2(x2), z, cb, cna));   // iw3-1
                float2 y1v = upk(pstep(h2_to_f2(x1), z, cb, cna));  // iw3-2
                float2 y0 = upk(pstep(h2_to_f2(x0), z, cb, cna));   // iw3-3
                int jl = 7 - g4;
                w0[ln * 9 + jl] = make_float4(y0.x, y1v.x, y2.x, y3.x);
                w1[ln * 9 + jl] = make_float4(y0.y, y1v.y, y2.y, y3.y);
            }
            __syncwarp();
            #pragma unroll
            for (int l = 0; l < 8; l++) {
                int q = l * 32 + ln;
                int tt = q >> 3, j = q & 7;
                int cc = wcb + tt;
                int base2 = cc * CL + iwb + 4 * j;
                *reinterpret_cast<float4*>(o0 + base2) = w0[tt * 9 + j];
                *reinterpret_cast<float4*>(o1 + base2) = w1[tt * 9 + j];
            }
            __syncwarp();
        }
    }
}

extern "C" void kernel_launch(void* const* d_in, const int* in_sizes, int n_in,
                              void* d_out, int out_size) {
    const float* x = (const float*)d_in[0];
    const float* b = (const float*)d_in[1];
    const float* a = (const float*)d_in[2];
    float* out = (float*)d_out;

    static bool attr_done = false;
    if (!attr_done) {
        cudaFuncSetAttribute(fwd_k, cudaFuncAttributeMaxDynamicSharedMemorySize, SMEM_STG);
        cudaFuncSetAttribute(bwd_k, cudaFuncAttributeMaxDynamicSharedMemorySize, SMEM_STG);
        attr_done = true;
    }

    fwd_k<<<GRID, NTH, SMEM_STG>>>(x, b, a);
    bwd_k<<<GRID, NTH, SMEM_STG>>>(out, b, a);
}

// round 15
// speedup vs baseline: 1.4604x; 1.2503x over previous
#include <cuda_runtime.h>
#include <cuda_fp16.h>

// Problem constants
#define BB   512
#define TT   65536
#define CL   256                  // chunk length (samples per thread)
#define NC   (TT / CL)            // 256 chunks per row
#define WUS  4                    // warm-up stages (128 samples; truncation ~3.5e-5)
#define NTH  128                  // 4 warps; each warp owns 32 chunks
#define NRP  (BB / 2)             // 256 row pairs
#define GRID (NRP * 2)            // 512 blocks

#define BUF_F4   (NTH * 9)
#define SMEM_STG (2 * BUF_F4 * 16)    // 36864 bytes

typedef unsigned long long u64f;
typedef unsigned int u32h;

// Intermediate: y1 transposed-packed in HALF precision: yt[iw * NC + c] is a
// half2 packing the two rows of the pair (lo=row0, hi=row1). 64 MB -> fits L2.
__device__ __align__(16) u32h g_y1t[(size_t)NRP * TT];

// ---------------------------------------------------------------------------
#define FFMA2(d, a, b, c) asm("fma.rn.f32x2 %0, %1, %2, %3;" : "=l"(d) : "l"(a), "l"(b), "l"(c))

__device__ __forceinline__ u64f pk2(float lo, float hi) {
    u64f r; asm("mov.b64 %0, {%1, %2};" : "=l"(r) : "f"(lo), "f"(hi)); return r;
}
__device__ __forceinline__ float2 upk(u64f v) {
    float2 r; asm("mov.b64 {%0, %1}, %2;" : "=f"(r.x), "=f"(r.y) : "l"(v)); return r;
}

// packed f32x2 -> half2 (lo stays low)
__device__ __forceinline__ u32h f2_to_h2(u64f v) {
    float2 f = upk(v);
    u32h r;
    asm("cvt.rn.f16x2.f32 %0, %1, %2;" : "=r"(r) : "f"(f.y), "f"(f.x));
    return r;
}
// half2 -> packed f32x2
__device__ __forceinline__ u64f h2_to_f2(u32h v) {
    float lo, hi;
    asm("{\n\t.reg .f16 l, h;\n\tmov.b32 {l, h}, %2;\n\t"
        "cvt.f32.f16 %0, l;\n\tcvt.f32.f16 %1, h;\n\t}"
        : "=f"(lo), "=f"(hi) : "r"(v));
    return pk2(lo, hi);
}

__device__ __forceinline__ u64f pstep(u64f x, u64f* z, const u64f* cb, const u64f* cna) {
    u64f y, t;
    FFMA2(y, cb[0], x, z[0]);
    #pragma unroll
    for (int i = 0; i < 7; i++) {
        FFMA2(t, cb[i + 1], x, z[i + 1]);
        FFMA2(z[i], cna[i], y, t);
    }
    u64f zz = 0ULL;
    FFMA2(t, cb[8], x, zz);
    FFMA2(z[7], cna[7], y, t);
    return y;
}

__device__ __forceinline__ void load_coef_inline(const float* __restrict__ bp,
                                                 const float* __restrict__ ap,
                                                 u64f* cb, u64f* cna) {
    float inv = 1.0f / __ldg(&ap[0]);
    #pragma unroll
    for (int i = 0; i < 9; i++) {
        float bn = __ldg(&bp[i]) * inv;
        cb[i] = pk2(bn, bn);
    }
    #pragma unroll
    for (int i = 1; i < 9; i++) {
        float an = -(__ldg(&ap[i]) * inv);
        cna[i - 1] = pk2(an, an);
    }
}

// ---------------------------------------------------------------------------
// fwd: warp-autonomous. Warm-up = 128 samples preceding the chunk, then 256
// own samples; y written to y1T in HALF2 (coalesced STG.32). x loaded with
// __ldcs (streaming, evict-first) so it never evicts y1t lines from L2.
// ---------------------------------------------------------------------------
__global__ void __launch_bounds__(NTH) fwd_k(const float* __restrict__ x,
                                             const float* __restrict__ bp,
                                             const float* __restrict__ ap) {
    extern __shared__ char smc[];
    float4* b0 = (float4*)smc;
    float4* b1 = b0 + BUF_F4;

    int rp = blockIdx.x >> 1, h = blockIdx.x & 1, t = threadIdx.x;
    int w = t >> 5, ln = t & 31;
    int wcb = (h * 4 + w) * 32;          // warp's first chunk
    int c = wcb + ln;                    // this lane's chunk
    const float* p0 = x + (size_t)(rp * 2) * TT;
    const float* p1 = p0 + TT;
    u32h* yt = g_y1t + (size_t)rp * TT;

    float4* w0 = b0 + w * (32 * 9);      // warp-private staging, row0
    float4* w1 = b1 + w * (32 * 9);      // row1

    u64f cb[9], cna[8];
    load_coef_inline(bp, ap, cb, cna);

    u64f z[8];
    #pragma unroll
    for (int i2 = 0; i2 < 8; i2++) z[i2] = 0ULL;

    #pragma unroll 1
    for (int k = 0; k < 8 + WUS; k++) {
        // cooperative warp load: local slot tt gets stage (wcb+tt)*8 + k - WUS
        #pragma unroll
        for (int l = 0; l < 8; l++) {
            int q = l * 32 + ln;
            int tt = q >> 3, j = q & 7;
            int sg = (wcb + tt) * 8 + (k - WUS);
            float4 va = make_float4(0.f, 0.f, 0.f, 0.f);
            float4 vb = va;
            if (sg >= 0) {
                int base = sg * 32 + 4 * j;
                va = __ldcs(reinterpret_cast<const float4*>(p0 + base));
                vb = __ldcs(reinterpret_cast<const float4*>(p1 + base));
            }
            w0[tt * 9 + j] = va;
            w1[tt * 9 + j] = vb;
        }
        __syncwarp();
        if (k < WUS) {
            #pragma unroll
            for (int j2 = 0; j2 < 8; j2++) {
                float4 a4 = w0[ln * 9 + j2];
                float4 c4 = w1[ln * 9 + j2];
                pstep(pk2(a4.x, c4.x), z, cb, cna);
                pstep(pk2(a4.y, c4.y), z, cb, cna);
                pstep(pk2(a4.z, c4.z), z, cb, cna);
                pstep(pk2(a4.w, c4.w), z, cb, cna);
            }
        } else {
            #pragma unroll
            for (int j2 = 0; j2 < 8; j2++) {
                float4 a4 = w0[ln * 9 + j2];
                float4 c4 = w1[ln * 9 + j2];
                u64f yp0 = pstep(pk2(a4.x, c4.x), z, cb, cna);
                u64f yp1 = pstep(pk2(a4.y, c4.y), z, cb, cna);
                u64f yp2 = pstep(pk2(a4.z, c4.z), z, cb, cna);
                u64f yp3 = pstep(pk2(a4.w, c4.w), z, cb, cna);
                int iw = (k - WUS) * 32 + 4 * j2;    // within-chunk index 0..255
                yt[(size_t)(iw + 0) * NC + c] = f2_to_h2(yp0);
                yt[(size_t)(iw + 1) * NC + c] = f2_to_h2(yp1);
                yt[(size_t)(iw + 2) * NC + c] = f2_to_h2(yp2);
                yt[(size_t)(iw + 3) * NC + c] = f2_to_h2(yp3);
            }
        }
        __syncwarp();
    }
}

// ---------------------------------------------------------------------------
// bwd: warp-autonomous time-reversed filter over half2 y1T (mostly L2-hit).
// Direct coalesced LDG.32 with rolling register prefetch; fp32 math after
// unpack. Output written with __stcs (streaming) via warp-private smem stage.
// ---------------------------------------------------------------------------
__global__ void __launch_bounds__(NTH) bwd_k(float* __restrict__ out,
                                             const float* __restrict__ bp,
                                             const float* __restrict__ ap) {
    extern __shared__ char smc[];
    float4* b0 = (float4*)smc;
    float4* b1 = b0 + BUF_F4;

    int rp = blockIdx.x >> 1, h = blockIdx.x & 1, t = threadIdx.x;
    int w = t >> 5, ln = t & 31;
    int wcb = (h * 4 + w) * 32;
    int c = wcb + ln;                    // this lane's chunk
    const u32h* yt = g_y1t + (size_t)rp * TT;
    float* o0 = out + (size_t)(rp * 2) * TT;
    float* o1 = o0 + TT;

    float4* w0 = b0 + w * (32 * 9);
    float4* w1 = b1 + w * (32 * 9);

    u64f cb[9], cna[8];
    load_coef_inline(bp, ap, cb, cna);

    u64f z[8];
    #pragma unroll
    for (int i2 = 0; i2 < 8; i2++) z[i2] = 0ULL;

    // ---- warm-up: chunk c+1, iw = 127 down to 0, rolling prefetch ----
    {
        bool valid = (c + 1 < NC);
        const u32h* base = yt + (valid ? (c + 1) : c);
        u32h nx0, nx1, nx2, nx3;
        nx3 = valid ? base[(size_t)127 * NC] : 0u;
        nx2 = valid ? base[(size_t)126 * NC] : 0u;
        nx1 = valid ? base[(size_t)125 * NC] : 0u;
        nx0 = valid ? base[(size_t)124 * NC] : 0u;
        #pragma unroll 1
        for (int p = 0; p < WUS * 8; p++) {
            u32h x3 = nx3, x2 = nx2, x1 = nx1, x0 = nx0;
            int niw3 = 127 - 4 * (p + 1);
            if (p + 1 < WUS * 8) {
                nx3 = valid ? base[(size_t)(niw3 - 0) * NC] : 0u;
                nx2 = valid ? base[(size_t)(niw3 - 1) * NC] : 0u;
                nx1 = valid ? base[(size_t)(niw3 - 2) * NC] : 0u;
                nx0 = valid ? base[(size_t)(niw3 - 3) * NC] : 0u;
            }
            pstep(h2_to_f2(x3), z, cb, cna);
            pstep(h2_to_f2(x2), z, cb, cna);
            pstep(h2_to_f2(x1), z, cb, cna);
            pstep(h2_to_f2(x0), z, cb, cna);
        }
    }

    // ---- own chunk: iw = 255 down to 0, prefetch; warp-staged output ----
    {
        const u32h* base = yt + c;
        u32h nx0, nx1, nx2, nx3;
        nx3 = base[(size_t)255 * NC];
        nx2 = base[(size_t)254 * NC];
        nx1 = base[(size_t)253 * NC];
        nx0 = base[(size_t)252 * NC];
        #pragma unroll 1
        for (int g = 0; g < 8; g++) {
            int iwb = 224 - 32 * g;          // base of this 32-sample group
            #pragma unroll
            for (int g4 = 0; g4 < 8; g4++) {
                u32h x3 = nx3, x2 = nx2, x1 = nx1, x0 = nx0;
                int iw3 = iwb + 31 - 4 * g4;
                int niw3 = iw3 - 4;
                if (niw3 >= 3) {
                    nx3 = base[(size_t)(niw3 - 0) * NC];
                    nx2 = base[(size_t)(niw3 - 1) * NC];
                    nx1 = base[(size_t)(niw3 - 2) * NC];
                    nx0 = base[(size_t)(niw3 - 3) * NC];
                }
                float2 y3 = upk(pstep(h2_to_f2(x3), z, cb, cna));   // iw3
                float2 y2 = upk(pstep(h2_to_f2(x2), z, cb, cna));   // iw3-1
                float2 y1v = upk(pstep(h2_to_f2(x1), z, cb, cna));  // iw3-2
                float2 y0 = upk(pstep(h2_to_f2(x0), z, cb, cna));   // iw3-3
                int jl = 7 - g4;
                w0[ln * 9 + jl] = make_float4(y0.x, y1v.x, y2.x, y3.x);
                w1[ln * 9 + jl] = make_float4(y0.y, y1v.y, y2.y, y3.y);
            }
            __syncwarp();
            #pragma unroll
            for (int l = 0; l < 8; l++) {
                int q = l * 32 + ln;
                int tt = q >> 3, j = q & 7;
                int cc = wcb + tt;
                int base2 = cc * CL + iwb + 4 * j;
                __stcs(reinterpret_cast<float4*>(o0 + base2), w0[tt * 9 + j]);
                __stcs(reinterpret_cast<float4*>(o1 + base2), w1[tt * 9 + j]);
            }
            __syncwarp();
        }
    }
}

extern "C" void kernel_launch(void* const* d_in, const int* in_sizes, int n_in,
                              void* d_out, int out_size) {
    const float* x = (const float*)d_in[0];
    const float* b = (const float*)d_in[1];
    const float* a = (const float*)d_in[2];
    float* out = (float*)d_out;

    static bool attr_done = false;
    if (!attr_done) {
        cudaFuncSetAttribute(fwd_k, cudaFuncAttributeMaxDynamicSharedMemorySize, SMEM_STG);
        cudaFuncSetAttribute(bwd_k, cudaFuncAttributeMaxDynamicSharedMemorySize, SMEM_STG);
        attr_done = true;
    }

    fwd_k<<<GRID, NTH, SMEM_STG>>>(x, b, a);
    bwd_k<<<GRID, NTH, SMEM_STG>>>(out, b, a);
}

// round 16
// speedup vs baseline: 1.5263x; 1.0451x over previous
#include <cuda_runtime.h>
#include <cuda_fp16.h>

// Problem constants
#define BB   512
#define TT   65536
#define CL   256                  // chunk length (samples per thread)
#define NC   (TT / CL)            // 256 chunks per row
#define WUS  4                    // warm-up stages (128 samples; truncation ~3.5e-5)
#define NTH  128                  // 4 warps; each warp owns 32 chunks
#define NRP  (BB / 2)             // 256 row pairs
#define GRID (NRP * 2)            // 512 blocks

#define BUF_F4   (NTH * 9)
#define SMEM_STG (2 * BUF_F4 * 16)    // 36864 bytes

typedef unsigned long long u64f;
typedef unsigned int u32h;

// Intermediate: y1 in half2, 4-wide vectorized transposed layout:
// yt4[(iw>>2) * NC + c] = uint4{h2(iw), h2(iw+1), h2(iw+2), h2(iw+3)}
// for chunk c. 64 MB total -> fits L2.
__device__ __align__(16) uint4 g_y1t4[(size_t)NRP * TT / 4];

// ---------------------------------------------------------------------------
#define FFMA2(d, a, b, c) asm("fma.rn.f32x2 %0, %1, %2, %3;" : "=l"(d) : "l"(a), "l"(b), "l"(c))

__device__ __forceinline__ u64f pk2(float lo, float hi) {
    u64f r; asm("mov.b64 %0, {%1, %2};" : "=l"(r) : "f"(lo), "f"(hi)); return r;
}
__device__ __forceinline__ float2 upk(u64f v) {
    float2 r; asm("mov.b64 {%0, %1}, %2;" : "=f"(r.x), "=f"(r.y) : "l"(v)); return r;
}

// packed f32x2 -> half2 (lo stays low)
__device__ __forceinline__ u32h f2_to_h2(u64f v) {
    float2 f = upk(v);
    u32h r;
    asm("cvt.rn.f16x2.f32 %0, %1, %2;" : "=r"(r) : "f"(f.y), "f"(f.x));
    return r;
}
// half2 -> packed f32x2
__device__ __forceinline__ u64f h2_to_f2(u32h v) {
    float lo, hi;
    asm("{\n\t.reg .f16 l, h;\n\tmov.b32 {l, h}, %2;\n\t"
        "cvt.f32.f16 %0, l;\n\tcvt.f32.f16 %1, h;\n\t}"
        : "=f"(lo), "=f"(hi) : "r"(v));
    return pk2(lo, hi);
}

__device__ __forceinline__ u64f pstep(u64f x, u64f* z, const u64f* cb, const u64f* cna) {
    u64f y, t;
    FFMA2(y, cb[0], x, z[0]);
    #pragma unroll
    for (int i = 0; i < 7; i++) {
        FFMA2(t, cb[i + 1], x, z[i + 1]);
        FFMA2(z[i], cna[i], y, t);
    }
    u64f zz = 0ULL;
    FFMA2(t, cb[8], x, zz);
    FFMA2(z[7], cna[7], y, t);
    return y;
}

__device__ __forceinline__ void load_coef_inline(const float* __restrict__ bp,
                                                 const float* __restrict__ ap,
                                                 u64f* cb, u64f* cna) {
    float inv = 1.0f / __ldg(&ap[0]);
    #pragma unroll
    for (int i = 0; i < 9; i++) {
        float bn = __ldg(&bp[i]) * inv;
        cb[i] = pk2(bn, bn);
    }
    #pragma unroll
    for (int i = 1; i < 9; i++) {
        float an = -(__ldg(&ap[i]) * inv);
        cna[i - 1] = pk2(an, an);
    }
}

// ---------------------------------------------------------------------------
// fwd: warp-autonomous. Warm-up = 128 samples preceding the chunk, then 256
// own samples; y written to y1t4 as ONE STG.128 per 4 samples. x loaded with
// __ldcs (streaming) so it never evicts y1t lines from L2.
// ---------------------------------------------------------------------------
__global__ void __launch_bounds__(NTH) fwd_k(const float* __restrict__ x,
                                             const float* __restrict__ bp,
                                             const float* __restrict__ ap) {
    extern __shared__ char smc[];
    float4* b0 = (float4*)smc;
    float4* b1 = b0 + BUF_F4;

    int rp = blockIdx.x >> 1, h = blockIdx.x & 1, t = threadIdx.x;
    int w = t >> 5, ln = t & 31;
    int wcb = (h * 4 + w) * 32;          // warp's first chunk
    int c = wcb + ln;                    // this lane's chunk
    const float* p0 = x + (size_t)(rp * 2) * TT;
    const float* p1 = p0 + TT;
    uint4* yt4 = g_y1t4 + (size_t)rp * (TT / 4);

    float4* w0 = b0 + w * (32 * 9);      // warp-private staging, row0
    float4* w1 = b1 + w * (32 * 9);      // row1

    u64f cb[9], cna[8];
    load_coef_inline(bp, ap, cb, cna);

    u64f z[8];
    #pragma unroll
    for (int i2 = 0; i2 < 8; i2++) z[i2] = 0ULL;

    #pragma unroll 1
    for (int k = 0; k < 8 + WUS; k++) {
        // cooperative warp load: local slot tt gets stage (wcb+tt)*8 + k - WUS
        #pragma unroll
        for (int l = 0; l < 8; l++) {
            int q = l * 32 + ln;
            int tt = q >> 3, j = q & 7;
            int sg = (wcb + tt) * 8 + (k - WUS);
            float4 va = make_float4(0.f, 0.f, 0.f, 0.f);
            float4 vb = va;
            if (sg >= 0) {
                int base = sg * 32 + 4 * j;
                va = __ldcs(reinterpret_cast<const float4*>(p0 + base));
                vb = __ldcs(reinterpret_cast<const float4*>(p1 + base));
            }
            w0[tt * 9 + j] = va;
            w1[tt * 9 + j] = vb;
        }
        __syncwarp();
        if (k < WUS) {
            #pragma unroll
            for (int j2 = 0; j2 < 8; j2++) {
                float4 a4 = w0[ln * 9 + j2];
                float4 c4 = w1[ln * 9 + j2];
                pstep(pk2(a4.x, c4.x), z, cb, cna);
                pstep(pk2(a4.y, c4.y), z, cb, cna);
                pstep(pk2(a4.z, c4.z), z, cb, cna);
                pstep(pk2(a4.w, c4.w), z, cb, cna);
            }
        } else {
            #pragma unroll
            for (int j2 = 0; j2 < 8; j2++) {
                float4 a4 = w0[ln * 9 + j2];
                float4 c4 = w1[ln * 9 + j2];
                uint4 pkv;
                pkv.x = f2_to_h2(pstep(pk2(a4.x, c4.x), z, cb, cna));
                pkv.y = f2_to_h2(pstep(pk2(a4.y, c4.y), z, cb, cna));
                pkv.z = f2_to_h2(pstep(pk2(a4.z, c4.z), z, cb, cna));
                pkv.w = f2_to_h2(pstep(pk2(a4.w, c4.w), z, cb, cna));
                int iw = (k - WUS) * 32 + 4 * j2;    // within-chunk index 0..255
                yt4[(size_t)(iw >> 2) * NC + c] = pkv;
            }
        }
        __syncwarp();
    }
}

// ---------------------------------------------------------------------------
// bwd: warp-autonomous time-reversed filter over vectorized y1t4: one LDG.128
// per 4 samples (rolling register prefetch), fp32 math after unpack. Output
// written with __stcs via warp-private smem stage (+__syncwarp only).
// ---------------------------------------------------------------------------
__global__ void __launch_bounds__(NTH) bwd_k(float* __restrict__ out,
                                             const float* __restrict__ bp,
                                             const float* __restrict__ ap) {
    extern __shared__ char smc[];
    float4* b0 = (float4*)smc;
    float4* b1 = b0 + BUF_F4;

    int rp = blockIdx.x >> 1, h = blockIdx.x & 1, t = threadIdx.x;
    int w = t >> 5, ln = t & 31;
    int wcb = (h * 4 + w) * 32;
    int c = wcb + ln;                    // this lane's chunk
    const uint4* yt4 = g_y1t4 + (size_t)rp * (TT / 4);
    float* o0 = out + (size_t)(rp * 2) * TT;
    float* o1 = o0 + TT;

    float4* w0 = b0 + w * (32 * 9);
    float4* w1 = b1 + w * (32 * 9);

    u64f cb[9], cna[8];
    load_coef_inline(bp, ap, cb, cna);

    u64f z[8];
    #pragma unroll
    for (int i2 = 0; i2 < 8; i2++) z[i2] = 0ULL;

    const uint4 zero4 = make_uint4(0u, 0u, 0u, 0u);

    // ---- warm-up: chunk c+1, packs 31..0 (iw 127..0), rolling prefetch ----
    {
        bool valid = (c + 1 < NC);
        const uint4* base = yt4 + (valid ? (c + 1) : c);
        uint4 nx = valid ? base[(size_t)31 * NC] : zero4;
        #pragma unroll 1
        for (int p = 0; p < WUS * 8; p++) {
            uint4 cur = nx;
            if (p + 1 < WUS * 8)
                nx = valid ? base[(size_t)(30 - p) * NC] : zero4;
            pstep(h2_to_f2(cur.w), z, cb, cna);
            pstep(h2_to_f2(cur.z), z, cb, cna);
            pstep(h2_to_f2(cur.y), z, cb, cna);
            pstep(h2_to_f2(cur.x), z, cb, cna);
        }
    }

    // ---- own chunk: packs 63..0 (iw 255..0), prefetch; staged output ----
    {
        const uint4* base = yt4 + c;
        uint4 nx = base[(size_t)63 * NC];
        #pragma unroll 1
        for (int g = 0; g < 8; g++) {
            int iwb = 224 - 32 * g;          // base of this 32-sample group
            #pragma unroll
            for (int g4 = 0; g4 < 8; g4++) {
                int p = g * 8 + g4;          // 0..63, pack index 63-p
                uint4 cur = nx;
                if (p + 1 < 64)
                    nx = base[(size_t)(62 - p) * NC];
                float2 y3 = upk(pstep(h2_to_f2(cur.w), z, cb, cna));   // iw3
                float2 y2 = upk(pstep(h2_to_f2(cur.z), z, cb, cna));   // iw3-1
                float2 y1v = upk(pstep(h2_to_f2(cur.y), z, cb, cna));  // iw3-2
                float2 y0 = upk(pstep(h2_to_f2(cur.x), z, cb, cna));   // iw3-3
                int jl = 7 - g4;
                w0[ln * 9 + jl] = make_float4(y0.x, y1v.x, y2.x, y3.x);
                w1[ln * 9 + jl] = make_float4(y0.y, y1v.y, y2.y, y3.y);
            }
            __syncwarp();
            #pragma unroll
            for (int l = 0; l < 8; l++) {
                int q = l * 32 + ln;
                int tt = q >> 3, j = q & 7;
                int cc = wcb + tt;
                int base2 = cc * CL + iwb + 4 * j;
                __stcs(reinterpret_cast<float4*>(o0 + base2), w0[tt * 9 + j]);
                __stcs(reinterpret_cast<float4*>(o1 + base2), w1[tt * 9 + j]);
            }
            __syncwarp();
        }
    }
}

extern "C" void kernel_launch(void* const* d_in, const int* in_sizes, int n_in,
                              void* d_out, int out_size) {
    const float* x = (const float*)d_in[0];
    const float* b = (const float*)d_in[1];
    const float* a = (const float*)d_in[2];
    float* out = (float*)d_out;

    static bool attr_done = false;
    if (!attr_done) {
        cudaFuncSetAttribute(fwd_k, cudaFuncAttributeMaxDynamicSharedMemorySize, SMEM_STG);
        cudaFuncSetAttribute(bwd_k, cudaFuncAttributeMaxDynamicSharedMemorySize, SMEM_STG);
        attr_done = true;
    }

    fwd_k<<<GRID, NTH, SMEM_STG>>>(x, b, a);
    bwd_k<<<GRID, NTH, SMEM_STG>>>(out, b, a);
}